// round 14
// baseline (speedup 1.0000x reference)
#include <cuda_runtime.h>
#include <cuda_bf16.h>
#include <stdint.h>

#define NB 64
#define TT 25
#define LL 196
#define VOC 32000
#define EMB 512
#define PROJD 1024
#define DEC 1024
#define NSTEP 24

// ---------------- device state (no allocations allowed) ----------------
// Weights bf16, GATE-PERMUTED rows: permuted row p = jblk*32 + jr*4 + q
// (j = jblk*8+jr, gate q in {i,f,g,o}) <-> original row q*1024 + j.
__device__ __nv_bfloat16 d_wcat0[4096 * 2560];      // layer0 [Wih | Whh]
__device__ __nv_bfloat16 d_wcat12[2][4096 * 2048];  // layers 1,2
__device__ __nv_bfloat16 d_pw[(long)VOC * DEC];     // out_W bf16
__device__ __nv_bfloat16 d_kbf[(long)NB * LL * DEC];
__device__ __nv_bfloat16 d_vbf[(long)NB * LL * PROJD];
__device__ float d_bsum[3][4096];                   // b_ih + b_hh (original order)
__device__ __nv_bfloat16 d_xc0[NB * 2560];          // [emb | ctx | h0]
__device__ __nv_bfloat16 d_xc1[NB * 2048];          // [h0_new | h1]
__device__ __nv_bfloat16 d_xc2[NB * 2048];          // [h1_new | h2]
__device__ __nv_bfloat16 d_hlastb[(long)NSTEP * NB * DEC];
__device__ float d_cbuf[3][NB * DEC];
__device__ float d_h2[NB * DEC];

__device__ __forceinline__ float sigmf(float x) { return 1.0f / (1.0f + expf(-x)); }

__device__ __forceinline__ uint32_t smem_u32(const void* p) {
    uint32_t a;
    asm("{ .reg .u64 t; cvta.to.shared.u64 t, %1; cvt.u32.u64 %0, t; }" : "=r"(a) : "l"(p));
    return a;
}
#define CPA16(d, s) asm volatile("cp.async.ca.shared.global [%0], [%1], 16;" :: "r"(d), "l"(s))
#define CP_COMMIT() asm volatile("cp.async.commit_group;" ::: "memory")
#define CP_WAIT(n) asm volatile("cp.async.wait_group %0;" :: "n"(n) : "memory")

#define LDSM4(r0, r1, r2, r3, addr) \
    asm volatile("ldmatrix.sync.aligned.m8n8.x4.shared.b16 {%0,%1,%2,%3}, [%4];" \
                 : "=r"(r0), "=r"(r1), "=r"(r2), "=r"(r3) : "r"(addr))

// C[16x8] += A[16x16] * B[16x8], bf16 inputs, fp32 accum
__device__ __forceinline__ void mma_bf16(float* c, const uint32_t* a, uint32_t b0, uint32_t b1) {
    asm volatile(
        "mma.sync.aligned.m16n8k16.row.col.f32.bf16.bf16.f32 "
        "{%0,%1,%2,%3}, {%4,%5,%6,%7}, {%8,%9}, {%0,%1,%2,%3};"
        : "+f"(c[0]), "+f"(c[1]), "+f"(c[2]), "+f"(c[3])
        : "r"(a[0]), "r"(a[1]), "r"(a[2]), "r"(a[3]), "r"(b0), "r"(b1));
}

// ---------------- single fused conversion kernel ----------------
__global__ void conv_all(const float4* __restrict__ Wih0, const float4* __restrict__ Whh0,
                         const float4* __restrict__ Wihr, const float4* __restrict__ Whhr,
                         const float4* __restrict__ outW, const float4* __restrict__ keys,
                         const float4* __restrict__ values,
                         const float4* __restrict__ bih0, const float4* __restrict__ bhh0,
                         const float4* __restrict__ bihr, const float4* __restrict__ bhhr) {
    const long N0 = 2621440L;            // w0: 4096 x 640 granules
    const long N1 = N0 + 2097152L;       // w1
    const long N2 = N1 + 2097152L;       // w2
    const long N3 = N2 + 8192000L;       // pw
    const long N4 = N3 + 3211264L;       // keys
    const long N5 = N4 + 3211264L;       // values
    const long N6 = N5 + 3072L;          // biases
    for (long i = (long)blockIdx.x * blockDim.x + threadIdx.x; i < N6;
         i += (long)gridDim.x * blockDim.x) {
        float4 v;
        __nv_bfloat16* dst;
        if (i < N0) {
            long o = i;
            int p = (int)(o / 640), k4 = (int)(o - (long)p * 640);
            int r = (p & 3) * 1024 + (p >> 5) * 8 + ((p >> 2) & 7);
            v = (k4 < 384) ? Wih0[(long)r * 384 + k4] : Whh0[(long)r * 256 + (k4 - 384)];
            dst = d_wcat0 + o * 4;
        } else if (i < N2) {
            int lay = (i < N1) ? 0 : 1;
            long o = i - (lay ? N1 : N0);
            int p = (int)(o / 512), k4 = (int)(o - (long)p * 512);
            int r = (p & 3) * 1024 + (p >> 5) * 8 + ((p >> 2) & 7) + lay * 4096;
            v = (k4 < 256) ? Wihr[(long)r * 256 + k4] : Whhr[(long)r * 256 + (k4 - 256)];
            dst = d_wcat12[lay] + o * 4;
        } else if (i < N3) {
            long o = i - N2; v = outW[o]; dst = d_pw + o * 4;
        } else if (i < N4) {
            long o = i - N3; v = keys[o]; dst = d_kbf + o * 4;
        } else if (i < N5) {
            long o = i - N4; v = values[o]; dst = d_vbf + o * 4;
        } else {
            long o = i - N5;
            int lay = (int)(o >> 10), r4 = (int)(o & 1023);
            float4 a, b;
            if (lay == 0)      { a = bih0[r4];        b = bhh0[r4]; }
            else if (lay == 1) { a = bihr[r4];        b = bhhr[r4]; }
            else               { a = bihr[1024 + r4]; b = bhhr[1024 + r4]; }
            *(float4*)&d_bsum[lay][r4 * 4] =
                make_float4(a.x + b.x, a.y + b.y, a.z + b.z, a.w + b.w);
            continue;
        }
        __nv_bfloat162* d2 = (__nv_bfloat162*)dst;
        d2[0] = __nv_bfloat162(__float2bfloat16_rn(v.x), __float2bfloat16_rn(v.y));
        d2[1] = __nv_bfloat162(__float2bfloat16_rn(v.z), __float2bfloat16_rn(v.w));
    }
}

// ---------------- init ----------------
__global__ void init_state(const float* __restrict__ ih, const float* __restrict__ ic,
                           const float* __restrict__ ictx, const float* __restrict__ emb) {
    int idx = blockIdx.x * blockDim.x + threadIdx.x;
    if (idx >= NB * 2560) return;
    int n = idx / 2560, j = idx % 2560;
    __nv_bfloat16 bv;
    if (j < 512) bv = __float2bfloat16_rn(emb[512 + j]);  // <start> = token 1
    else if (j < 1536) bv = __float2bfloat16_rn(ictx[j - 512]);
    else bv = __float2bfloat16_rn(ih[j - 1536]);
    d_xc0[idx] = bv;
    if (j < 1024) {
        d_xc1[n * 2048 + 1024 + j] = __float2bfloat16_rn(ih[1024 + j]);
        d_xc2[n * 2048 + 1024 + j] = __float2bfloat16_rn(ih[2048 + j]);
        d_cbuf[0][n * 1024 + j] = ic[j];
        d_cbuf[1][n * 1024 + j] = ic[1024 + j];
        d_cbuf[2][n * 1024 + j] = ic[2048 + j];
        d_h2[n * 1024 + j] = ih[2048 + j];
    }
}

__global__ void out0_kernel(float* __restrict__ out) {
    int idx = blockIdx.x * blockDim.x + threadIdx.x;
    if (idx < NB * VOC) {
        int n = idx / VOC, v = idx % VOC;
        out[(long)n * TT * VOC + v] = (v == 1) ? 10000.0f : 0.0f;
    }
}

// ---------------- fused LSTM: 512 thr, 2 K-groups of 8 warps, 12-stage pipeline ----------------
// grid 128 (jblk), CTA tile 64 batch x 32 permuted rows, chunk = 64 K-cols.
// stage: X 64x64 bf16 (row stride 144B) = 9216B + W 32x64 = 4608B -> 13824B, x12 stages.
#define LSTG 13824
#define LS_NST 12
#define LS_SMEM (LS_NST * LSTG)

template <int LAYER>
__device__ __forceinline__ void lstm_ld(char* smem, int stg, int k0, int tid, int bn) {
    uint32_t st = smem_u32(smem) + stg * LSTG;
    const __nv_bfloat16* Xc = (LAYER == 0) ? d_xc0 : (LAYER == 1) ? d_xc1 : d_xc2;
    const __nv_bfloat16* Wc = (LAYER == 0) ? d_wcat0 : d_wcat12[LAYER - 1];
    const int Ktot = (LAYER == 0) ? 2560 : 2048;
    {   // X: 64 rows x 8 granules = 512 -> one per thread
        int row = tid >> 3, c = tid & 7;
        CPA16(st + row * 144 + c * 16, Xc + (long)row * Ktot + k0 + c * 8);
    }
    if (tid < 256) {  // W: 32 rows x 8 granules
        int row = tid >> 3, c = tid & 7;
        CPA16(st + 9216 + row * 144 + c * 16, Wc + ((long)bn * 32 + row) * Ktot + k0 + c * 8);
    }
}

template <int LAYER>
__global__ __launch_bounds__(512) void lstm_fused(int step) {
    extern __shared__ char smem[];
    __shared__ float sbias[32];
    const int Ktot = (LAYER == 0) ? 2560 : 2048;
    const int NCH = Ktot / 64;
    const int NIT = NCH / 2;
    const int tid = threadIdx.x;
    const int w = tid >> 5, lane = tid & 31, g = lane >> 2, tig = lane & 3;
    const int kg = w >> 3;           // K-group 0/1
    const int wl = w & 7;            // warp within group
    const int bn = blockIdx.x;
    const int m0 = (wl & 3) * 16, n0 = (wl >> 2) * 16;
    const uint32_t sbase = smem_u32(smem);

    if (tid < 32) sbias[tid] = d_bsum[LAYER][(tid & 3) * 1024 + bn * 8 + (tid >> 2)];

    float acc[2][4] = {};

    const uint32_t a_off =
        (uint32_t)((m0 + (lane & 7) + ((lane >> 3) & 1) * 8) * 144 + (lane >> 4) * 16);
    const uint32_t b_off =
        (uint32_t)(9216 + (n0 + (lane & 7) + ((lane >> 4) & 1) * 8) * 144 +
                   ((lane >> 3) & 1) * 16);

#pragma unroll
    for (int i = 0; i < 10; i++) {
        lstm_ld<LAYER>(smem, i, i * 64, tid, bn);
        CP_COMMIT();
    }

    for (int i = 0; i < NIT; i++) {
        int last = 2 * i + 9;
        if (last > NCH - 1) last = NCH - 1;
        int p = last - 2 * i - 1;  // pending groups allowed so chunks 2i,2i+1 are done
        if (p >= 8) CP_WAIT(8);
        else if (p == 7) CP_WAIT(7);
        else if (p == 6) CP_WAIT(6);
        else if (p == 5) CP_WAIT(5);
        else if (p == 4) CP_WAIT(4);
        else if (p == 3) CP_WAIT(3);
        else if (p == 2) CP_WAIT(2);
        else if (p == 1) CP_WAIT(1);
        else CP_WAIT(0);
        __syncthreads();
        if (2 * i + 10 < NCH) {
            lstm_ld<LAYER>(smem, (2 * i + 10) % LS_NST, (2 * i + 10) * 64, tid, bn);
            CP_COMMIT();
        }
        if (2 * i + 11 < NCH) {
            lstm_ld<LAYER>(smem, (2 * i + 11) % LS_NST, (2 * i + 11) * 64, tid, bn);
            CP_COMMIT();
        }
        int c = 2 * i + kg;
        uint32_t xb = sbase + (c % LS_NST) * LSTG;
#pragma unroll
        for (int kk = 0; kk < 4; kk++) {
            uint32_t a[4], b[4];
            LDSM4(a[0], a[1], a[2], a[3], xb + a_off + kk * 32);
            LDSM4(b[0], b[1], b[2], b[3], xb + b_off + kk * 32);
            mma_bf16(acc[0], a, b[0], b[1]);
            mma_bf16(acc[1], a, b[2], b[3]);
        }
    }

    // dump partial frags: group kg -> fp32 tile T_kg [64][36] (stage area, all loads drained)
    __syncthreads();
    float* T = (float*)smem + kg * 2304;
#pragma unroll
    for (int nf = 0; nf < 2; nf++) {
        int col = n0 + nf * 8 + tig * 2;
        T[(m0 + g) * 36 + col] = acc[nf][0];
        T[(m0 + g) * 36 + col + 1] = acc[nf][1];
        T[(m0 + g + 8) * 36 + col] = acc[nf][2];
        T[(m0 + g + 8) * 36 + col + 1] = acc[nf][3];
    }
    __syncthreads();

    // gate epilogue: 512 (n,j) cells, 1 per thread; row layout jr*4 + q; sum K-group partials
    {
        float* T0 = (float*)smem;
        float* T1 = T0 + 2304;
        int n = tid >> 3, jr = tid & 7;
        int j = bn * 8 + jr;
        float iv = T0[n * 36 + jr * 4 + 0] + T1[n * 36 + jr * 4 + 0] + sbias[jr * 4 + 0];
        float fv = T0[n * 36 + jr * 4 + 1] + T1[n * 36 + jr * 4 + 1] + sbias[jr * 4 + 1];
        float gv = T0[n * 36 + jr * 4 + 2] + T1[n * 36 + jr * 4 + 2] + sbias[jr * 4 + 2];
        float ov = T0[n * 36 + jr * 4 + 3] + T1[n * 36 + jr * 4 + 3] + sbias[jr * 4 + 3];
        float c2 = sigmf(fv) * d_cbuf[LAYER][n * 1024 + j] + sigmf(iv) * tanhf(gv);
        float h2 = sigmf(ov) * tanhf(c2);
        d_cbuf[LAYER][n * 1024 + j] = c2;
        __nv_bfloat16 hb = __float2bfloat16_rn(h2);
        if (LAYER == 0) {
            d_xc1[n * 2048 + j] = hb;
            d_xc0[n * 2560 + 1536 + j] = hb;
        } else if (LAYER == 1) {
            d_xc2[n * 2048 + j] = hb;
            d_xc1[n * 2048 + 1024 + j] = hb;
        } else {
            d_xc2[n * 2048 + 1024 + j] = hb;
            d_h2[n * 1024 + j] = h2;
            d_hlastb[((long)step * NB + n) * 1024 + j] = hb;
        }
    }
}

// ---------------- fused attention: energy + softmax + ctx + x0 build (grid 64) ----------------
__global__ __launch_bounds__(256) void attn_kernel(const int* __restrict__ captions,
                                                   const float* __restrict__ emb,
                                                   int next_step) {
    int n = blockIdx.x;
    int tid = threadIdx.x, wd = tid >> 5, lane = tid & 31;
    __shared__ float hs[DEC];
    __shared__ float e[LL];
    __shared__ float red[8], red2[8];
    for (int k = tid; k < DEC; k += 256) hs[k] = d_h2[n * DEC + k];
    __syncthreads();
    for (int r = wd; r < LL; r += 8) {
        const uint4* kr = (const uint4*)(d_kbf + ((long)n * LL + r) * DEC);
        float s = 0.f;
#pragma unroll
        for (int i = 0; i < 4; i++) {
            uint4 v = kr[lane + i * 32];
            int kb = (lane + i * 32) * 8;
            __nv_bfloat162 p0 = *(__nv_bfloat162*)&v.x;
            __nv_bfloat162 p1 = *(__nv_bfloat162*)&v.y;
            __nv_bfloat162 p2 = *(__nv_bfloat162*)&v.z;
            __nv_bfloat162 p3 = *(__nv_bfloat162*)&v.w;
            s += __bfloat162float(p0.x) * hs[kb] + __bfloat162float(p0.y) * hs[kb + 1] +
                 __bfloat162float(p1.x) * hs[kb + 2] + __bfloat162float(p1.y) * hs[kb + 3] +
                 __bfloat162float(p2.x) * hs[kb + 4] + __bfloat162float(p2.y) * hs[kb + 5] +
                 __bfloat162float(p3.x) * hs[kb + 6] + __bfloat162float(p3.y) * hs[kb + 7];
        }
#pragma unroll
        for (int o = 16; o; o >>= 1) s += __shfl_xor_sync(0xffffffffu, s, o);
        if (lane == 0) e[r] = s;
    }
    __syncthreads();
    float v = (tid < LL) ? e[tid] : -3.4e38f;
    float m = v;
#pragma unroll
    for (int o = 16; o; o >>= 1) m = fmaxf(m, __shfl_xor_sync(0xffffffffu, m, o));
    if (lane == 0) red[wd] = m;
    __syncthreads();
    if (tid < 8) {
        float mm = red[tid];
#pragma unroll
        for (int o = 4; o; o >>= 1) mm = fmaxf(mm, __shfl_xor_sync(0xffu, mm, o));
        if (tid == 0) red[0] = mm;
    }
    __syncthreads();
    float gm = red[0];
    float ex = (tid < LL) ? expf(v - gm) : 0.f;
    float s = ex;
#pragma unroll
    for (int o = 16; o; o >>= 1) s += __shfl_xor_sync(0xffffffffu, s, o);
    if (lane == 0) red2[wd] = s;
    __syncthreads();
    if (tid < 8) {
        float ss = red2[tid];
#pragma unroll
        for (int o = 4; o; o >>= 1) ss += __shfl_xor_sync(0xffu, ss, o);
        if (tid == 0) red2[0] = ss;
    }
    __syncthreads();
    if (tid < LL) e[tid] = ex / red2[0];
    __syncthreads();
    // ctx: thread owns 4 contiguous cols (uint2 = 4 bf16 per row)
    const uint2* vp = (const uint2*)(d_vbf + (long)n * LL * PROJD) + tid;
    float a0 = 0.f, a1 = 0.f, a2 = 0.f, a3 = 0.f;
#pragma unroll 2
    for (int l = 0; l < LL; l++) {
        float wl = e[l];
        uint2 vv = vp[(long)l * 256];
        __nv_bfloat162 q0 = *(__nv_bfloat162*)&vv.x;
        __nv_bfloat162 q1 = *(__nv_bfloat162*)&vv.y;
        a0 += wl * __bfloat162float(q0.x); a1 += wl * __bfloat162float(q0.y);
        a2 += wl * __bfloat162float(q1.x); a3 += wl * __bfloat162float(q1.y);
    }
    __nv_bfloat162* xo = (__nv_bfloat162*)(d_xc0 + n * 2560 + 512 + tid * 4);
    xo[0] = __nv_bfloat162(__float2bfloat16_rn(a0), __float2bfloat16_rn(a1));
    xo[1] = __nv_bfloat162(__float2bfloat16_rn(a2), __float2bfloat16_rn(a3));
    // refresh embedding half of x0 for the next token
    int tok = captions[n * TT + next_step];
    for (int k = tid; k < EMB; k += 256)
        d_xc0[n * 2560 + k] = __float2bfloat16_rn(emb[(long)tok * EMB + k]);
}

// ---------------- projection (bf16 mma, 4-stage): out = hlast @ out_W^T ----------------
#define PSTAGE 20480
#define PJ_SMEM (4 * PSTAGE)

__device__ __forceinline__ void proj_ld(uint32_t st, int bm, int bn, int k0, int tid) {
#pragma unroll
    for (int i = 0; i < 2; i++) {
        int gI = tid + i * 256;
        int row = gI >> 2, c = gI & 3;
        CPA16(st + row * 80 + c * 16, d_hlastb + (long)(bm * 128 + row) * DEC + k0 + c * 8);
    }
#pragma unroll
    for (int i = 0; i < 2; i++) {
        int gI = tid + i * 256;
        int row = gI >> 2, c = gI & 3;
        CPA16(st + 10240 + row * 80 + c * 16, d_pw + (long)(bn * 128 + row) * DEC + k0 + c * 8);
    }
}

__global__ __launch_bounds__(256) void proj_mma(const float* __restrict__ bias,
                                                float* __restrict__ out) {
    extern __shared__ char smem[];
    uint32_t sb = smem_u32(smem);
    const int tid = threadIdx.x;
    const int w = tid >> 5, lane = tid & 31, g = lane >> 2, tig = lane & 3;
    const int wm = w >> 2, wn = w & 3;
    const int bm = blockIdx.x, bn = blockIdx.y;

    float acc[4][4][4] = {};

    proj_ld(sb, bm, bn, 0, tid);  CP_COMMIT();
    proj_ld(sb + PSTAGE, bm, bn, 32, tid); CP_COMMIT();
    proj_ld(sb + 2 * PSTAGE, bm, bn, 64, tid); CP_COMMIT();

    for (int c = 0; c < 32; c++) {
        if (c + 2 < 32) CP_WAIT(2);
        else if (c + 1 < 32) CP_WAIT(1);
        else CP_WAIT(0);
        __syncthreads();
        if (c + 3 < 32) { proj_ld(sb + ((c + 3) & 3) * PSTAGE, bm, bn, (c + 3) * 32, tid); CP_COMMIT(); }
        const uint32_t* Au = (const uint32_t*)(smem + (c & 3) * PSTAGE);
        const uint32_t* Bu = (const uint32_t*)(smem + (c & 3) * PSTAGE + 10240);
#pragma unroll
        for (int ks = 0; ks < 2; ks++) {
            int k8 = ks * 8;
            uint32_t a[4][4];
#pragma unroll
            for (int mi = 0; mi < 4; mi++) {
                int r = (wm * 64 + mi * 16 + g) * 20;
                a[mi][0] = Au[r + k8 + tig];
                a[mi][1] = Au[r + 160 + k8 + tig];
                a[mi][2] = Au[r + k8 + tig + 4];
                a[mi][3] = Au[r + 160 + k8 + tig + 4];
            }
#pragma unroll
            for (int nj = 0; nj < 4; nj++) {
                int nr = (wn * 32 + nj * 8 + g) * 20;
                uint32_t b0 = Bu[nr + k8 + tig], b1 = Bu[nr + k8 + tig + 4];
#pragma unroll
                for (int mi = 0; mi < 4; mi++) mma_bf16(acc[mi][nj], a[mi], b0, b1);
            }
        }
    }

#pragma unroll
    for (int mi = 0; mi < 4; mi++) {
#pragma unroll
        for (int nj = 0; nj < 4; nj++) {
            int m0 = bm * 128 + wm * 64 + mi * 16 + g;
            int vv = bn * 128 + wn * 32 + nj * 8 + tig * 2;
            float b0 = bias[vv], b1 = bias[vv + 1];
            {
                int step = m0 >> 6, nn = m0 & 63;
                *(float2*)(out + ((long)nn * TT + step + 1) * VOC + vv) =
                    make_float2(acc[mi][nj][0] + b0, acc[mi][nj][1] + b1);
            }
            {
                int m1 = m0 + 8;
                int step = m1 >> 6, nn = m1 & 63;
                *(float2*)(out + ((long)nn * TT + step + 1) * VOC + vv) =
                    make_float2(acc[mi][nj][2] + b0, acc[mi][nj][3] + b1);
            }
        }
    }
}

// ---------------- launch ----------------
extern "C" void kernel_launch(void* const* d_in, const int* in_sizes, int n_in,
                              void* d_out, int out_size) {
    int sh = (n_in >= 19) ? 0 : 1;
    const float* keys     = (const float*)d_in[0];
    const float* values   = (const float*)d_in[1];
    const int*   captions = (const int*)d_in[3];
    const float* emb      = (const float*)d_in[5 - sh];
    const float* W_ih0    = (const float*)d_in[6 - sh];
    const float* W_hh0    = (const float*)d_in[7 - sh];
    const float* b_ih0    = (const float*)d_in[8 - sh];
    const float* b_hh0    = (const float*)d_in[9 - sh];
    const float* W_ih_r   = (const float*)d_in[10 - sh];
    const float* W_hh_r   = (const float*)d_in[11 - sh];
    const float* b_ih_r   = (const float*)d_in[12 - sh];
    const float* b_hh_r   = (const float*)d_in[13 - sh];
    const float* out_W    = (const float*)d_in[14 - sh];
    const float* out_b    = (const float*)d_in[15 - sh];
    const float* init_h   = (const float*)d_in[16 - sh];
    const float* init_c   = (const float*)d_in[17 - sh];
    const float* init_ctx = (const float*)d_in[18 - sh];
    float* out = (float*)d_out;

    cudaFuncSetAttribute(lstm_fused<0>, cudaFuncAttributeMaxDynamicSharedMemorySize, LS_SMEM);
    cudaFuncSetAttribute(lstm_fused<1>, cudaFuncAttributeMaxDynamicSharedMemorySize, LS_SMEM);
    cudaFuncSetAttribute(lstm_fused<2>, cudaFuncAttributeMaxDynamicSharedMemorySize, LS_SMEM);
    cudaFuncSetAttribute(proj_mma, cudaFuncAttributeMaxDynamicSharedMemorySize, PJ_SMEM);

    conv_all<<<2048, 256>>>((const float4*)W_ih0, (const float4*)W_hh0,
                            (const float4*)W_ih_r, (const float4*)W_hh_r,
                            (const float4*)out_W, (const float4*)keys, (const float4*)values,
                            (const float4*)b_ih0, (const float4*)b_hh0,
                            (const float4*)b_ih_r, (const float4*)b_hh_r);

    init_state<<<640, 256>>>(init_h, init_c, init_ctx, emb);
    out0_kernel<<<(NB * VOC + 255) / 256, 256>>>(out);

    for (int s = 0; s < NSTEP; s++) {
        lstm_fused<0><<<128, 512, LS_SMEM>>>(s);
        lstm_fused<1><<<128, 512, LS_SMEM>>>(s);
        lstm_fused<2><<<128, 512, LS_SMEM>>>(s);
        attn_kernel<<<64, 256>>>(captions, emb, s + 1);
    }

    proj_mma<<<dim3(12, 250), 256, PJ_SMEM>>>(out_b, out);
}

// round 15
// speedup vs baseline: 1.1835x; 1.1835x over previous
#include <cuda_runtime.h>
#include <cuda_bf16.h>
#include <stdint.h>

#define NB 64
#define TT 25
#define LL 196
#define VOC 32000
#define EMB 512
#define PROJD 1024
#define DEC 1024
#define NSTEP 24

// ---------------- device state (no allocations allowed) ----------------
// Weights bf16, GATE-PERMUTED rows: permuted row p = jblk*32 + jr*4 + q
// (j = jblk*8+jr, gate q in {i,f,g,o}) <-> original row q*1024 + j.
__device__ __nv_bfloat16 d_wcat0[4096 * 2560];      // layer0 [Wih | Whh]
__device__ __nv_bfloat16 d_wcat12[2][4096 * 2048];  // layers 1,2
__device__ __nv_bfloat16 d_pw[(long)VOC * DEC];     // out_W bf16
__device__ __nv_bfloat16 d_kbf[(long)NB * LL * DEC];
__device__ __nv_bfloat16 d_vbf[(long)NB * LL * PROJD];
__device__ float d_bsum[3][4096];                   // b_ih + b_hh (original order)
__device__ __nv_bfloat16 d_xc0[NB * 2560];          // [emb | ctx | h0]
__device__ __nv_bfloat16 d_xc1[NB * 2048];          // [h0_new | h1]
__device__ __nv_bfloat16 d_xc2[NB * 2048];          // [h1_new | h2]
__device__ __nv_bfloat16 d_hlastb[(long)NSTEP * NB * DEC];
__device__ float d_cbuf[3][NB * DEC];
__device__ float d_h2[NB * DEC];
__device__ float d_att[NB * LL];

__device__ __forceinline__ float sigmf(float x) { return 1.0f / (1.0f + expf(-x)); }

__device__ __forceinline__ uint32_t smem_u32(const void* p) {
    uint32_t a;
    asm("{ .reg .u64 t; cvta.to.shared.u64 t, %1; cvt.u32.u64 %0, t; }" : "=r"(a) : "l"(p));
    return a;
}
#define CPA16(d, s) asm volatile("cp.async.ca.shared.global [%0], [%1], 16;" :: "r"(d), "l"(s))
#define CP_COMMIT() asm volatile("cp.async.commit_group;" ::: "memory")
#define CP_WAIT(n) asm volatile("cp.async.wait_group %0;" :: "n"(n) : "memory")

#define LDSM4(r0, r1, r2, r3, addr) \
    asm volatile("ldmatrix.sync.aligned.m8n8.x4.shared.b16 {%0,%1,%2,%3}, [%4];" \
                 : "=r"(r0), "=r"(r1), "=r"(r2), "=r"(r3) : "r"(addr))

// C[16x8] += A[16x16] * B[16x8], bf16 inputs, fp32 accum
__device__ __forceinline__ void mma_bf16(float* c, const uint32_t* a, uint32_t b0, uint32_t b1) {
    asm volatile(
        "mma.sync.aligned.m16n8k16.row.col.f32.bf16.bf16.f32 "
        "{%0,%1,%2,%3}, {%4,%5,%6,%7}, {%8,%9}, {%0,%1,%2,%3};"
        : "+f"(c[0]), "+f"(c[1]), "+f"(c[2]), "+f"(c[3])
        : "r"(a[0]), "r"(a[1]), "r"(a[2]), "r"(a[3]), "r"(b0), "r"(b1));
}

// ---------------- single fused conversion kernel ----------------
__global__ void conv_all(const float4* __restrict__ Wih0, const float4* __restrict__ Whh0,
                         const float4* __restrict__ Wihr, const float4* __restrict__ Whhr,
                         const float4* __restrict__ outW, const float4* __restrict__ keys,
                         const float4* __restrict__ values,
                         const float4* __restrict__ bih0, const float4* __restrict__ bhh0,
                         const float4* __restrict__ bihr, const float4* __restrict__ bhhr) {
    const long N0 = 2621440L;            // w0: 4096 x 640 granules
    const long N1 = N0 + 2097152L;       // w1
    const long N2 = N1 + 2097152L;       // w2
    const long N3 = N2 + 8192000L;       // pw
    const long N4 = N3 + 3211264L;       // keys
    const long N5 = N4 + 3211264L;       // values
    const long N6 = N5 + 3072L;          // biases
    for (long i = (long)blockIdx.x * blockDim.x + threadIdx.x; i < N6;
         i += (long)gridDim.x * blockDim.x) {
        float4 v;
        __nv_bfloat16* dst;
        if (i < N0) {
            long o = i;
            int p = (int)(o / 640), k4 = (int)(o - (long)p * 640);
            int r = (p & 3) * 1024 + (p >> 5) * 8 + ((p >> 2) & 7);
            v = (k4 < 384) ? Wih0[(long)r * 384 + k4] : Whh0[(long)r * 256 + (k4 - 384)];
            dst = d_wcat0 + o * 4;
        } else if (i < N2) {
            int lay = (i < N1) ? 0 : 1;
            long o = i - (lay ? N1 : N0);
            int p = (int)(o / 512), k4 = (int)(o - (long)p * 512);
            int r = (p & 3) * 1024 + (p >> 5) * 8 + ((p >> 2) & 7) + lay * 4096;
            v = (k4 < 256) ? Wihr[(long)r * 256 + k4] : Whhr[(long)r * 256 + (k4 - 256)];
            dst = d_wcat12[lay] + o * 4;
        } else if (i < N3) {
            long o = i - N2; v = outW[o]; dst = d_pw + o * 4;
        } else if (i < N4) {
            long o = i - N3; v = keys[o]; dst = d_kbf + o * 4;
        } else if (i < N5) {
            long o = i - N4; v = values[o]; dst = d_vbf + o * 4;
        } else {
            long o = i - N5;
            int lay = (int)(o >> 10), r4 = (int)(o & 1023);
            float4 a, b;
            if (lay == 0)      { a = bih0[r4];        b = bhh0[r4]; }
            else if (lay == 1) { a = bihr[r4];        b = bhhr[r4]; }
            else               { a = bihr[1024 + r4]; b = bhhr[1024 + r4]; }
            *(float4*)&d_bsum[lay][r4 * 4] =
                make_float4(a.x + b.x, a.y + b.y, a.z + b.z, a.w + b.w);
            continue;
        }
        __nv_bfloat162* d2 = (__nv_bfloat162*)dst;
        d2[0] = __nv_bfloat162(__float2bfloat16_rn(v.x), __float2bfloat16_rn(v.y));
        d2[1] = __nv_bfloat162(__float2bfloat16_rn(v.z), __float2bfloat16_rn(v.w));
    }
}

// ---------------- init ----------------
__global__ void init_state(const float* __restrict__ ih, const float* __restrict__ ic,
                           const float* __restrict__ ictx, const float* __restrict__ emb) {
    int idx = blockIdx.x * blockDim.x + threadIdx.x;
    if (idx >= NB * 2560) return;
    int n = idx / 2560, j = idx % 2560;
    __nv_bfloat16 bv;
    if (j < 512) bv = __float2bfloat16_rn(emb[512 + j]);  // <start> = token 1
    else if (j < 1536) bv = __float2bfloat16_rn(ictx[j - 512]);
    else bv = __float2bfloat16_rn(ih[j - 1536]);
    d_xc0[idx] = bv;
    if (j < 1024) {
        d_xc1[n * 2048 + 1024 + j] = __float2bfloat16_rn(ih[1024 + j]);
        d_xc2[n * 2048 + 1024 + j] = __float2bfloat16_rn(ih[2048 + j]);
        d_cbuf[0][n * 1024 + j] = ic[j];
        d_cbuf[1][n * 1024 + j] = ic[1024 + j];
        d_cbuf[2][n * 1024 + j] = ic[2048 + j];
        d_h2[n * 1024 + j] = ih[2048 + j];
    }
}

__global__ void out0_kernel(float* __restrict__ out) {
    int idx = blockIdx.x * blockDim.x + threadIdx.x;
    if (idx < NB * VOC) {
        int n = idx / VOC, v = idx % VOC;
        out[(long)n * TT * VOC + v] = (v == 1) ? 10000.0f : 0.0f;
    }
}

// ---------------- fused LSTM: 512 thr; X ring 4 stages (thr 0-255), W ring 20 (thr 256-511) ----
// grid 128 (jblk), CTA tile 64 batch x 32 permuted rows, chunk = 64 K-cols.
// X stage 64x64 bf16 (stride 144B) = 9216B x4; W stage 32x64 = 4608B x20. Total 129024B.
#define XSTG 9216
#define WSTG 4608
#define W_BASE (4 * XSTG)
#define LS_SMEM (4 * XSTG + 20 * WSTG)

template <int LAYER>
__device__ __forceinline__ void lstm_ldX(char* smem, int stg, int k0, int tid) {
    uint32_t st = smem_u32(smem) + stg * XSTG;
    const __nv_bfloat16* Xc = (LAYER == 0) ? d_xc0 : (LAYER == 1) ? d_xc1 : d_xc2;
    const int Ktot = (LAYER == 0) ? 2560 : 2048;
#pragma unroll
    for (int i = 0; i < 2; i++) {
        int gI = tid + i * 256;
        int row = gI >> 3, c = gI & 7;
        CPA16(st + row * 144 + c * 16, Xc + (long)row * Ktot + k0 + c * 8);
    }
}

template <int LAYER>
__device__ __forceinline__ void lstm_ldW(char* smem, int stg, int k0, int t, int bn) {
    uint32_t st = smem_u32(smem) + W_BASE + stg * WSTG;
    const __nv_bfloat16* Wc = (LAYER == 0) ? d_wcat0 : d_wcat12[LAYER - 1];
    const int Ktot = (LAYER == 0) ? 2560 : 2048;
    int row = t >> 3, c = t & 7;
    CPA16(st + row * 144 + c * 16, Wc + ((long)bn * 32 + row) * Ktot + k0 + c * 8);
}

template <int LAYER>
__global__ __launch_bounds__(512) void lstm_fused(int step) {
    extern __shared__ char smem[];
    __shared__ float sbias[32];
    const int Ktot = (LAYER == 0) ? 2560 : 2048;
    const int NCH = Ktot / 64;
    const int tid = threadIdx.x;
    const int w = tid >> 5, lane = tid & 31, g = lane >> 2, tig = lane & 3;
    const int bn = blockIdx.x;
    const int m0 = (w & 3) * 16, n0 = (w >> 2) * 16;  // valid for compute warps 0-7
    const uint32_t sbase = smem_u32(smem);
    const bool isX = tid < 256;

    if (tid < 32) sbias[tid] = d_bsum[LAYER][(tid & 3) * 1024 + bn * 8 + (tid >> 2)];

    float acc[2][4] = {};

    // fragment offsets within a stage (compute warps 0-7 only)
    const uint32_t a_off =
        (uint32_t)((m0 + (lane & 7) + ((lane >> 3) & 1) * 8) * 144 + (lane >> 4) * 16);
    const uint32_t b_off =
        (uint32_t)((n0 + (lane & 7) + ((lane >> 4) & 1) * 8) * 144 + ((lane >> 3) & 1) * 16);

    // prologue: X 3 chunks ahead, W 19 chunks ahead (per-role commit groups)
    if (isX) {
#pragma unroll
        for (int i = 0; i < 3; i++) { lstm_ldX<LAYER>(smem, i, i * 64, tid); CP_COMMIT(); }
    } else {
        int t = tid - 256;
        for (int i = 0; i < 19; i++) {
            int k0 = i * 64;
            if (k0 > Ktot - 64) k0 = Ktot - 64;  // clamped tail loads land in dead slots
            lstm_ldW<LAYER>(smem, i, k0, t, bn);
            CP_COMMIT();
        }
    }

    for (int c = 0; c < NCH; c++) {
        // role-local waits guarantee chunk c resident; syncthreads joins roles
        if (isX) CP_WAIT(2); else CP_WAIT(18);
        __syncthreads();
        if (isX) {
            int k0 = (c + 3) * 64;
            if (k0 > Ktot - 64) k0 = Ktot - 64;
            lstm_ldX<LAYER>(smem, (c + 3) & 3, k0, tid);
            CP_COMMIT();
        } else {
            int k0 = (c + 19) * 64;
            if (k0 > Ktot - 64) k0 = Ktot - 64;
            lstm_ldW<LAYER>(smem, (c + 19) % 20, k0, tid - 256, bn);
            CP_COMMIT();
        }
        if (isX) {  // warps 0-7 compute
            uint32_t xb = sbase + (c & 3) * XSTG;
            uint32_t wb = sbase + W_BASE + (c % 20) * WSTG;
#pragma unroll
            for (int kk = 0; kk < 4; kk++) {
                uint32_t a[4], b[4];
                LDSM4(a[0], a[1], a[2], a[3], xb + a_off + kk * 32);
                LDSM4(b[0], b[1], b[2], b[3], wb + b_off + kk * 32);
                mma_bf16(acc[0], a, b[0], b[1]);
                mma_bf16(acc[1], a, b[2], b[3]);
            }
        }
    }

    // dump frags into fp32 smem tile [64 batch][32 rows], stride 36 (reuse X stage 0)
    __syncthreads();
    float* T = (float*)smem;
    if (isX) {
#pragma unroll
        for (int nf = 0; nf < 2; nf++) {
            int col = n0 + nf * 8 + tig * 2;
            T[(m0 + g) * 36 + col] = acc[nf][0];
            T[(m0 + g) * 36 + col + 1] = acc[nf][1];
            T[(m0 + g + 8) * 36 + col] = acc[nf][2];
            T[(m0 + g + 8) * 36 + col + 1] = acc[nf][3];
        }
    }
    __syncthreads();

    // gate epilogue: 512 (n,j) cells, 1 per thread; row layout jr*4 + q
    {
        int n = tid >> 3, jr = tid & 7;
        int j = bn * 8 + jr;
        float iv = T[n * 36 + jr * 4 + 0] + sbias[jr * 4 + 0];
        float fv = T[n * 36 + jr * 4 + 1] + sbias[jr * 4 + 1];
        float gv = T[n * 36 + jr * 4 + 2] + sbias[jr * 4 + 2];
        float ov = T[n * 36 + jr * 4 + 3] + sbias[jr * 4 + 3];
        float c2 = sigmf(fv) * d_cbuf[LAYER][n * 1024 + j] + sigmf(iv) * tanhf(gv);
        float h2 = sigmf(ov) * tanhf(c2);
        d_cbuf[LAYER][n * 1024 + j] = c2;
        __nv_bfloat16 hb = __float2bfloat16_rn(h2);
        if (LAYER == 0) {
            d_xc1[n * 2048 + j] = hb;
            d_xc0[n * 2560 + 1536 + j] = hb;
        } else if (LAYER == 1) {
            d_xc2[n * 2048 + j] = hb;
            d_xc1[n * 2048 + 1024 + j] = hb;
        } else {
            d_xc2[n * 2048 + 1024 + j] = hb;
            d_h2[n * 1024 + j] = h2;
            d_hlastb[((long)step * NB + n) * 1024 + j] = hb;
        }
    }
}

// ---------------- attention part 1: energy = keys . h2 (bf16 keys) ----------------
__global__ void energy_kernel() {
    int n = blockIdx.x;
    int l = blockIdx.y * 8 + (threadIdx.x >> 5);
    int lane = threadIdx.x & 31;
    __shared__ float hs[DEC];
    for (int k = threadIdx.x; k < DEC; k += 256) hs[k] = d_h2[n * DEC + k];
    __syncthreads();
    if (l >= LL) return;
    const uint4* kr = (const uint4*)(d_kbf + ((long)n * LL + l) * DEC);
    float s = 0.f;
#pragma unroll
    for (int i = 0; i < 4; i++) {
        uint4 v = kr[lane + i * 32];
        int kb = (lane + i * 32) * 8;
        __nv_bfloat162 p0 = *(__nv_bfloat162*)&v.x;
        __nv_bfloat162 p1 = *(__nv_bfloat162*)&v.y;
        __nv_bfloat162 p2 = *(__nv_bfloat162*)&v.z;
        __nv_bfloat162 p3 = *(__nv_bfloat162*)&v.w;
        s += __bfloat162float(p0.x) * hs[kb] + __bfloat162float(p0.y) * hs[kb + 1] +
             __bfloat162float(p1.x) * hs[kb + 2] + __bfloat162float(p1.y) * hs[kb + 3] +
             __bfloat162float(p2.x) * hs[kb + 4] + __bfloat162float(p2.y) * hs[kb + 5] +
             __bfloat162float(p3.x) * hs[kb + 6] + __bfloat162float(p3.y) * hs[kb + 7];
    }
#pragma unroll
    for (int o = 16; o; o >>= 1) s += __shfl_xor_sync(0xffffffffu, s, o);
    if (lane == 0) d_att[n * LL + l] = s;
}

// ---------------- attention part 2: softmax + ctx + x0 build ----------------
__global__ void softctx_kernel(const int* __restrict__ captions, const float* __restrict__ emb,
                               int next_step) {
    int n = blockIdx.x;
    int tid = threadIdx.x;
    int wid = tid >> 5, lane = tid & 31;
    __shared__ float e[LL];
    __shared__ float red[8], red2[8];
    float v = (tid < LL) ? d_att[n * LL + tid] : -3.4e38f;
    float m = v;
#pragma unroll
    for (int o = 16; o; o >>= 1) m = fmaxf(m, __shfl_xor_sync(0xffffffffu, m, o));
    if (lane == 0) red[wid] = m;
    __syncthreads();
    if (tid < 8) {
        float mm = red[tid];
#pragma unroll
        for (int o = 4; o; o >>= 1) mm = fmaxf(mm, __shfl_xor_sync(0xffu, mm, o));
        if (tid == 0) red[0] = mm;
    }
    __syncthreads();
    float gm = red[0];
    float ex = (tid < LL) ? expf(v - gm) : 0.f;
    float s = ex;
#pragma unroll
    for (int o = 16; o; o >>= 1) s += __shfl_xor_sync(0xffffffffu, s, o);
    if (lane == 0) red2[wid] = s;
    __syncthreads();
    if (tid < 8) {
        float ss = red2[tid];
#pragma unroll
        for (int o = 4; o; o >>= 1) ss += __shfl_xor_sync(0xffu, ss, o);
        if (tid == 0) red2[0] = ss;
    }
    __syncthreads();
    if (tid < LL) e[tid] = ex / red2[0];
    __syncthreads();
    int col = blockIdx.y * 256 + tid;
    const __nv_bfloat16* vp = d_vbf + (long)n * LL * PROJD + col;
    float acc = 0.f;
#pragma unroll 4
    for (int l = 0; l < LL; l++) acc += e[l] * __bfloat162float(vp[(long)l * PROJD]);
    d_xc0[n * 2560 + 512 + col] = __float2bfloat16_rn(acc);
    if (blockIdx.y == 0) {
        int tok = captions[n * TT + next_step];
        for (int k = tid; k < EMB; k += 256)
            d_xc0[n * 2560 + k] = __float2bfloat16_rn(emb[(long)tok * EMB + k]);
    }
}

// ---------------- projection (bf16 mma, 4-stage): out = hlast @ out_W^T ----------------
#define PSTAGE 20480
#define PJ_SMEM (4 * PSTAGE)

__device__ __forceinline__ void proj_ld(uint32_t st, int bm, int bn, int k0, int tid) {
#pragma unroll
    for (int i = 0; i < 2; i++) {
        int gI = tid + i * 256;
        int row = gI >> 2, c = gI & 3;
        CPA16(st + row * 80 + c * 16, d_hlastb + (long)(bm * 128 + row) * DEC + k0 + c * 8);
    }
#pragma unroll
    for (int i = 0; i < 2; i++) {
        int gI = tid + i * 256;
        int row = gI >> 2, c = gI & 3;
        CPA16(st + 10240 + row * 80 + c * 16, d_pw + (long)(bn * 128 + row) * DEC + k0 + c * 8);
    }
}

__global__ __launch_bounds__(256) void proj_mma(const float* __restrict__ bias,
                                                float* __restrict__ out) {
    extern __shared__ char smem[];
    uint32_t sb = smem_u32(smem);
    const int tid = threadIdx.x;
    const int w = tid >> 5, lane = tid & 31, g = lane >> 2, tig = lane & 3;
    const int wm = w >> 2, wn = w & 3;
    const int bm = blockIdx.x, bn = blockIdx.y;

    float acc[4][4][4] = {};

    proj_ld(sb, bm, bn, 0, tid);  CP_COMMIT();
    proj_ld(sb + PSTAGE, bm, bn, 32, tid); CP_COMMIT();
    proj_ld(sb + 2 * PSTAGE, bm, bn, 64, tid); CP_COMMIT();

    for (int c = 0; c < 32; c++) {
        if (c + 2 < 32) CP_WAIT(2);
        else if (c + 1 < 32) CP_WAIT(1);
        else CP_WAIT(0);
        __syncthreads();
        if (c + 3 < 32) { proj_ld(sb + ((c + 3) & 3) * PSTAGE, bm, bn, (c + 3) * 32, tid); CP_COMMIT(); }
        const uint32_t* Au = (const uint32_t*)(smem + (c & 3) * PSTAGE);
        const uint32_t* Bu = (const uint32_t*)(smem + (c & 3) * PSTAGE + 10240);
#pragma unroll
        for (int ks = 0; ks < 2; ks++) {
            int k8 = ks * 8;
            uint32_t a[4][4];
#pragma unroll
            for (int mi = 0; mi < 4; mi++) {
                int r = (wm * 64 + mi * 16 + g) * 20;
                a[mi][0] = Au[r + k8 + tig];
                a[mi][1] = Au[r + 160 + k8 + tig];
                a[mi][2] = Au[r + k8 + tig + 4];
                a[mi][3] = Au[r + 160 + k8 + tig + 4];
            }
#pragma unroll
            for (int nj = 0; nj < 4; nj++) {
                int nr = (wn * 32 + nj * 8 + g) * 20;
                uint32_t b0 = Bu[nr + k8 + tig], b1 = Bu[nr + k8 + tig + 4];
#pragma unroll
                for (int mi = 0; mi < 4; mi++) mma_bf16(acc[mi][nj], a[mi], b0, b1);
            }
        }
    }

#pragma unroll
    for (int mi = 0; mi < 4; mi++) {
#pragma unroll
        for (int nj = 0; nj < 4; nj++) {
            int m0 = bm * 128 + wm * 64 + mi * 16 + g;
            int vv = bn * 128 + wn * 32 + nj * 8 + tig * 2;
            float b0 = bias[vv], b1 = bias[vv + 1];
            {
                int step = m0 >> 6, nn = m0 & 63;
                *(float2*)(out + ((long)nn * TT + step + 1) * VOC + vv) =
                    make_float2(acc[mi][nj][0] + b0, acc[mi][nj][1] + b1);
            }
            {
                int m1 = m0 + 8;
                int step = m1 >> 6, nn = m1 & 63;
                *(float2*)(out + ((long)nn * TT + step + 1) * VOC + vv) =
                    make_float2(acc[mi][nj][2] + b0, acc[mi][nj][3] + b1);
            }
        }
    }
}

// ---------------- launch ----------------
extern "C" void kernel_launch(void* const* d_in, const int* in_sizes, int n_in,
                              void* d_out, int out_size) {
    int sh = (n_in >= 19) ? 0 : 1;
    const float* keys     = (const float*)d_in[0];
    const float* values   = (const float*)d_in[1];
    const int*   captions = (const int*)d_in[3];
    const float* emb      = (const float*)d_in[5 - sh];
    const float* W_ih0    = (const float*)d_in[6 - sh];
    const float* W_hh0    = (const float*)d_in[7 - sh];
    const float* b_ih0    = (const float*)d_in[8 - sh];
    const float* b_hh0    = (const float*)d_in[9 - sh];
    const float* W_ih_r   = (const float*)d_in[10 - sh];
    const float* W_hh_r   = (const float*)d_in[11 - sh];
    const float* b_ih_r   = (const float*)d_in[12 - sh];
    const float* b_hh_r   = (const float*)d_in[13 - sh];
    const float* out_W    = (const float*)d_in[14 - sh];
    const float* out_b    = (const float*)d_in[15 - sh];
    const float* init_h   = (const float*)d_in[16 - sh];
    const float* init_c   = (const float*)d_in[17 - sh];
    const float* init_ctx = (const float*)d_in[18 - sh];
    float* out = (float*)d_out;

    cudaFuncSetAttribute(lstm_fused<0>, cudaFuncAttributeMaxDynamicSharedMemorySize, LS_SMEM);
    cudaFuncSetAttribute(lstm_fused<1>, cudaFuncAttributeMaxDynamicSharedMemorySize, LS_SMEM);
    cudaFuncSetAttribute(lstm_fused<2>, cudaFuncAttributeMaxDynamicSharedMemorySize, LS_SMEM);
    cudaFuncSetAttribute(proj_mma, cudaFuncAttributeMaxDynamicSharedMemorySize, PJ_SMEM);

    conv_all<<<2048, 256>>>((const float4*)W_ih0, (const float4*)W_hh0,
                            (const float4*)W_ih_r, (const float4*)W_hh_r,
                            (const float4*)out_W, (const float4*)keys, (const float4*)values,
                            (const float4*)b_ih0, (const float4*)b_hh0,
                            (const float4*)b_ih_r, (const float4*)b_hh_r);

    init_state<<<640, 256>>>(init_h, init_c, init_ctx, emb);
    out0_kernel<<<(NB * VOC + 255) / 256, 256>>>(out);

    for (int s = 0; s < NSTEP; s++) {
        lstm_fused<0><<<128, 512, LS_SMEM>>>(s);
        lstm_fused<1><<<128, 512, LS_SMEM>>>(s);
        lstm_fused<2><<<128, 512, LS_SMEM>>>(s);
        energy_kernel<<<dim3(64, 25), 256>>>();
        softctx_kernel<<<dim3(64, 4), 256>>>(captions, emb, s + 1);
    }

    proj_mma<<<dim3(12, 250), 256, PJ_SMEM>>>(out_b, out);
}

// round 16
// speedup vs baseline: 1.3792x; 1.1654x over previous
#include <cuda_runtime.h>
#include <cuda_bf16.h>
#include <cuda_fp16.h>
#include <cuda_fp8.h>
#include <stdint.h>

#define NB 64
#define TT 25
#define LL 196
#define VOC 32000
#define EMB 512
#define PROJD 1024
#define DEC 1024
#define NSTEP 24

// ---------------- device state (no allocations allowed) ----------------
// LSTM weights: e4m3, value*64, GATE-PERMUTED rows p = jblk*32 + jr*4 + q
// (j = jblk*8+jr, gate q) <-> original row q*1024 + j, and K-INTERLEAVED within
// each 16-k block: byte i (t=i>>2, j2=i&3) holds k = 2t + (j2&1) + 8*(j2>>1),
// so one u32 LDS at offset tig*4 gives the f16-mma B k-pairs {2tig,2tig+1} and +8.
__device__ __align__(16) uint8_t d_w8_0[4096 * 2560];
__device__ __align__(16) uint8_t d_w8_12[2][4096 * 2048];
__device__ __nv_bfloat16 d_pw[(long)VOC * DEC];     // out_W bf16
__device__ __nv_bfloat16 d_kbf[(long)NB * LL * DEC];
__device__ __nv_bfloat16 d_vbf[(long)NB * LL * PROJD];
__device__ float d_bsum[3][4096];                   // b_ih + b_hh (original order)
__device__ __half d_xc0[NB * 2560];                 // [emb | ctx | h0]  (f16)
__device__ __half d_xc1[NB * 2048];                 // [h0_new | h1]
__device__ __half d_xc2[NB * 2048];                 // [h1_new | h2]
__device__ __nv_bfloat16 d_hlastb[(long)NSTEP * NB * DEC];
__device__ float d_cbuf[3][NB * DEC];
__device__ float d_h2[NB * DEC];
__device__ float d_att[NB * LL];

__device__ __forceinline__ float sigmf(float x) { return 1.0f / (1.0f + expf(-x)); }

__device__ __forceinline__ uint32_t smem_u32(const void* p) {
    uint32_t a;
    asm("{ .reg .u64 t; cvta.to.shared.u64 t, %1; cvt.u32.u64 %0, t; }" : "=r"(a) : "l"(p));
    return a;
}
#define CPA16(d, s) asm volatile("cp.async.ca.shared.global [%0], [%1], 16;" :: "r"(d), "l"(s))
#define CP_COMMIT() asm volatile("cp.async.commit_group;" ::: "memory")
#define CP_WAIT(n) asm volatile("cp.async.wait_group %0;" :: "n"(n) : "memory")

#define LDSM4(r0, r1, r2, r3, addr) \
    asm volatile("ldmatrix.sync.aligned.m8n8.x4.shared.b16 {%0,%1,%2,%3}, [%4];" \
                 : "=r"(r0), "=r"(r1), "=r"(r2), "=r"(r3) : "r"(addr))

// C[16x8] += A[16x16] * B[16x8], f16 inputs, fp32 accum
__device__ __forceinline__ void mma_f16(float* c, const uint32_t* a, uint32_t b0, uint32_t b1) {
    asm volatile(
        "mma.sync.aligned.m16n8k16.row.col.f32.f16.f16.f32 "
        "{%0,%1,%2,%3}, {%4,%5,%6,%7}, {%8,%9}, {%0,%1,%2,%3};"
        : "+f"(c[0]), "+f"(c[1]), "+f"(c[2]), "+f"(c[3])
        : "r"(a[0]), "r"(a[1]), "r"(a[2]), "r"(a[3]), "r"(b0), "r"(b1));
}

// 4x e4m3 (one u32) -> two f16x2 regs
__device__ __forceinline__ void cvt8to16(uint32_t w, uint32_t& lo, uint32_t& hi) {
    asm("{ .reg .b16 l, h;\n\t mov.b32 {l, h}, %2;\n\t"
        "cvt.rn.f16x2.e4m3x2 %0, l;\n\t cvt.rn.f16x2.e4m3x2 %1, h; }"
        : "=r"(lo), "=r"(hi) : "r"(w));
}

__device__ __forceinline__ int perm_row(int p) {
    return (p & 3) * 1024 + (p >> 5) * 8 + ((p >> 2) & 7);
}

// ---------------- single fused conversion kernel ----------------
// region A: weights -> fp8 (scaled x64, row-permuted, k-interleaved), 16 src floats/thread
// region B: pw/keys/values -> bf16, biases -> f32 sums (float4 granules)
__global__ void conv_all(const float* __restrict__ Wih0, const float* __restrict__ Whh0,
                         const float* __restrict__ Wihr, const float* __restrict__ Whhr,
                         const float4* __restrict__ outW, const float4* __restrict__ keys,
                         const float4* __restrict__ values,
                         const float4* __restrict__ bih0, const float4* __restrict__ bhh0,
                         const float4* __restrict__ bihr, const float4* __restrict__ bhhr) {
    const long NW0 = 655360L;                 // 4096 rows x 160 blocks
    const long NW  = NW0 + 1048576L;          // + 2 x 4096 x 128
    const long N3 = NW + 8192000L;            // pw granules
    const long N4 = N3 + 3211264L;            // keys
    const long N5 = N4 + 3211264L;            // values
    const long N6 = N5 + 3072L;               // biases
    for (long i = (long)blockIdx.x * blockDim.x + threadIdx.x; i < N6;
         i += (long)gridDim.x * blockDim.x) {
        if (i < NW) {  // ---- weight fp8 blocks ----
            const float* src;
            uint4* dst;
            int c16, Ka;
            if (i < NW0) {
                int p = (int)(i / 160); c16 = (int)(i - (long)p * 160);
                int r = perm_row(p);
                Ka = 96;  // Wih blocks (K=1536 -> 96 blocks)
                src = (c16 < Ka) ? Wih0 + (long)r * 1536 + c16 * 16
                                 : Whh0 + (long)r * 1024 + (c16 - Ka) * 16;
                dst = (uint4*)d_w8_0 + i;
            } else {
                long o = i - NW0;
                int lay = (int)(o >> 19);          // 524288 per layer
                int o2 = (int)(o & 524287);
                int p = o2 >> 7; c16 = o2 & 127;
                int r = perm_row(p) + lay * 4096;
                Ka = 64;  // Wihr blocks (K=1024 -> 64)
                src = (c16 < Ka) ? Wihr + (long)r * 1024 + c16 * 16
                                 : Whhr + (long)r * 1024 + (c16 - Ka) * 16;
                dst = (uint4*)d_w8_12[lay] + o2;
            }
            float f[16];
#pragma unroll
            for (int q = 0; q < 4; q++) {
                float4 v = ((const float4*)src)[q];
                f[q * 4] = v.x; f[q * 4 + 1] = v.y; f[q * 4 + 2] = v.z; f[q * 4 + 3] = v.w;
            }
            union { uint8_t b[16]; uint4 u; } out;
#pragma unroll
            for (int b = 0; b < 16; b++) {
                int t = b >> 2, j2 = b & 3;
                int k = 2 * t + (j2 & 1) + 8 * (j2 >> 1);
                out.b[b] = (uint8_t)__nv_cvt_float_to_fp8(f[k] * 64.0f, __NV_SATFINITE, __NV_E4M3);
            }
            *dst = out.u;
            continue;
        }
        float4 v;
        __nv_bfloat16* dst;
        long o;
        if (i < N3)      { o = i - NW; v = outW[o];  dst = d_pw + o * 4; }
        else if (i < N4) { o = i - N3; v = keys[o];  dst = d_kbf + o * 4; }
        else if (i < N5) { o = i - N4; v = values[o]; dst = d_vbf + o * 4; }
        else {
            o = i - N5;
            int lay = (int)(o >> 10), r4 = (int)(o & 1023);
            float4 a, b;
            if (lay == 0)      { a = bih0[r4];        b = bhh0[r4]; }
            else if (lay == 1) { a = bihr[r4];        b = bhhr[r4]; }
            else               { a = bihr[1024 + r4]; b = bhhr[1024 + r4]; }
            *(float4*)&d_bsum[lay][r4 * 4] =
                make_float4(a.x + b.x, a.y + b.y, a.z + b.z, a.w + b.w);
            continue;
        }
        __nv_bfloat162* d2 = (__nv_bfloat162*)dst;
        d2[0] = __nv_bfloat162(__float2bfloat16_rn(v.x), __float2bfloat16_rn(v.y));
        d2[1] = __nv_bfloat162(__float2bfloat16_rn(v.z), __float2bfloat16_rn(v.w));
    }
}

// ---------------- init ----------------
__global__ void init_state(const float* __restrict__ ih, const float* __restrict__ ic,
                           const float* __restrict__ ictx, const float* __restrict__ emb) {
    int idx = blockIdx.x * blockDim.x + threadIdx.x;
    if (idx >= NB * 2560) return;
    int n = idx / 2560, j = idx % 2560;
    __half hv;
    if (j < 512) hv = __float2half_rn(emb[512 + j]);  // <start> = token 1
    else if (j < 1536) hv = __float2half_rn(ictx[j - 512]);
    else hv = __float2half_rn(ih[j - 1536]);
    d_xc0[idx] = hv;
    if (j < 1024) {
        d_xc1[n * 2048 + 1024 + j] = __float2half_rn(ih[1024 + j]);
        d_xc2[n * 2048 + 1024 + j] = __float2half_rn(ih[2048 + j]);
        d_cbuf[0][n * 1024 + j] = ic[j];
        d_cbuf[1][n * 1024 + j] = ic[1024 + j];
        d_cbuf[2][n * 1024 + j] = ic[2048 + j];
        d_h2[n * 1024 + j] = ih[2048 + j];
    }
}

__global__ void out0_kernel(float* __restrict__ out) {
    int idx = blockIdx.x * blockDim.x + threadIdx.x;
    if (idx < NB * VOC) {
        int n = idx / VOC, v = idx % VOC;
        out[(long)n * TT * VOC + v] = (v == 1) ? 10000.0f : 0.0f;
    }
}

// ---------------- fused LSTM: 256 thr, 10-stage pipeline, f16 X + fp8 W ----------------
// grid 128 (jblk). CTA tile 64 batch x 32 permuted rows, chunk = 64 K-cols.
// stage: X 64x64 f16 (stride 144B) = 9216B + W 32x64 fp8 (stride 80B) = 2560B -> 11776B x10.
#define XSTG 9216
#define LSTG 11776
#define LS_NST 10
#define LS_SMEM (LS_NST * LSTG)

template <int LAYER>
__device__ __forceinline__ void lstm_ld(char* smem, int stg, int k0, int tid, int bn) {
    uint32_t st = smem_u32(smem) + stg * LSTG;
    const __half* Xc = (LAYER == 0) ? d_xc0 : (LAYER == 1) ? d_xc1 : d_xc2;
    const uint8_t* Wc = (LAYER == 0) ? d_w8_0 : d_w8_12[LAYER - 1];
    const int Ktot = (LAYER == 0) ? 2560 : 2048;
#pragma unroll
    for (int i = 0; i < 2; i++) {  // X: 64 rows x 8 granules of 16B
        int gI = tid + i * 256;
        int row = gI >> 3, c = gI & 7;
        CPA16(st + row * 144 + c * 16, Xc + (long)row * Ktot + k0 + c * 8);
    }
    if (tid < 128) {  // W fp8: 32 rows x 4 granules of 16B
        int row = tid >> 2, c = tid & 3;
        CPA16(st + XSTG + row * 80 + c * 16, Wc + ((long)bn * 32 + row) * Ktot + k0 + c * 16);
    }
}

template <int LAYER>
__global__ __launch_bounds__(256) void lstm_fused(int step) {
    extern __shared__ char smem[];
    __shared__ float sbias[32];
    const int Ktot = (LAYER == 0) ? 2560 : 2048;
    const int NCH = Ktot / 64;
    const int tid = threadIdx.x;
    const int w = tid >> 5, lane = tid & 31, g = lane >> 2, tig = lane & 3;
    const int bn = blockIdx.x;
    const int m0 = (w & 3) * 16, n0 = (w >> 2) * 16;
    const uint32_t sbase = smem_u32(smem);

    if (tid < 32) sbias[tid] = d_bsum[LAYER][(tid & 3) * 1024 + bn * 8 + (tid >> 2)];

    float acc[2][4] = {};

    const uint32_t a_off =
        (uint32_t)((m0 + (lane & 7) + ((lane >> 3) & 1) * 8) * 144 + (lane >> 4) * 16);
    // W LDS offsets per nf (row = n0 + nf*8 + g, fp8 stride 80)
    const uint32_t w_off0 = (uint32_t)(XSTG + (n0 + g) * 80 + tig * 4);
    const uint32_t w_off1 = (uint32_t)(XSTG + (n0 + 8 + g) * 80 + tig * 4);

#pragma unroll
    for (int i = 0; i < 9; i++) {
        lstm_ld<LAYER>(smem, i, i * 64, tid, bn);
        CP_COMMIT();
    }

    for (int c = 0; c < NCH; c++) {
        int d = NCH - 1 - c;
        if (d >= 8) CP_WAIT(8);
        else if (d == 7) CP_WAIT(7);
        else if (d == 6) CP_WAIT(6);
        else if (d == 5) CP_WAIT(5);
        else if (d == 4) CP_WAIT(4);
        else if (d == 3) CP_WAIT(3);
        else if (d == 2) CP_WAIT(2);
        else if (d == 1) CP_WAIT(1);
        else CP_WAIT(0);
        __syncthreads();
        if (c + 9 < NCH) {
            lstm_ld<LAYER>(smem, (c + 9) % LS_NST, (c + 9) * 64, tid, bn);
            CP_COMMIT();
        }
        uint32_t xb = sbase + (c % LS_NST) * LSTG;
#pragma unroll
        for (int kk = 0; kk < 4; kk++) {
            uint32_t a[4];
            LDSM4(a[0], a[1], a[2], a[3], xb + a_off + kk * 32);
            uint32_t w8a = *(const uint32_t*)(smem + (c % LS_NST) * LSTG +
                                              (w_off0 - 0) + kk * 16);
            uint32_t w8b = *(const uint32_t*)(smem + (c % LS_NST) * LSTG +
                                              (w_off1 - 0) + kk * 16);
            uint32_t b0, b1, b2, b3;
            cvt8to16(w8a, b0, b1);
            cvt8to16(w8b, b2, b3);
            mma_f16(acc[0], a, b0, b1);
            mma_f16(acc[1], a, b2, b3);
        }
    }

    // dump frags into fp32 smem tile [64 batch][32 rows], stride 36 (reuse stage 0 X area)
    __syncthreads();
    float* T = (float*)smem;
#pragma unroll
    for (int nf = 0; nf < 2; nf++) {
        int col = n0 + nf * 8 + tig * 2;
        T[(m0 + g) * 36 + col] = acc[nf][0];
        T[(m0 + g) * 36 + col + 1] = acc[nf][1];
        T[(m0 + g + 8) * 36 + col] = acc[nf][2];
        T[(m0 + g + 8) * 36 + col + 1] = acc[nf][3];
    }
    __syncthreads();

    // gate epilogue: 512 (n,j) cells, 2 per thread; row layout jr*4 + q; scale 1/64
    const float SC = 0.015625f;
#pragma unroll
    for (int u = 0; u < 2; u++) {
        int idx = tid * 2 + u;
        int n = idx >> 3, jr = idx & 7;
        int j = bn * 8 + jr;
        float iv = T[n * 36 + jr * 4 + 0] * SC + sbias[jr * 4 + 0];
        float fv = T[n * 36 + jr * 4 + 1] * SC + sbias[jr * 4 + 1];
        float gv = T[n * 36 + jr * 4 + 2] * SC + sbias[jr * 4 + 2];
        float ov = T[n * 36 + jr * 4 + 3] * SC + sbias[jr * 4 + 3];
        float c2 = sigmf(fv) * d_cbuf[LAYER][n * 1024 + j] + sigmf(iv) * tanhf(gv);
        float h2 = sigmf(ov) * tanhf(c2);
        d_cbuf[LAYER][n * 1024 + j] = c2;
        __half hb = __float2half_rn(h2);
        if (LAYER == 0) {
            d_xc1[n * 2048 + j] = hb;
            d_xc0[n * 2560 + 1536 + j] = hb;
        } else if (LAYER == 1) {
            d_xc2[n * 2048 + j] = hb;
            d_xc1[n * 2048 + 1024 + j] = hb;
        } else {
            d_xc2[n * 2048 + 1024 + j] = hb;
            d_h2[n * 1024 + j] = h2;
            d_hlastb[((long)step * NB + n) * 1024 + j] = __float2bfloat16_rn(h2);
        }
    }
}

// ---------------- attention part 1: energy = keys . h2 (bf16 keys) ----------------
__global__ void energy_kernel() {
    int n = blockIdx.x;
    int l = blockIdx.y * 8 + (threadIdx.x >> 5);
    int lane = threadIdx.x & 31;
    __shared__ float hs[DEC];
    for (int k = threadIdx.x; k < DEC; k += 256) hs[k] = d_h2[n * DEC + k];
    __syncthreads();
    if (l >= LL) return;
    const uint4* kr = (const uint4*)(d_kbf + ((long)n * LL + l) * DEC);
    float s = 0.f;
#pragma unroll
    for (int i = 0; i < 4; i++) {
        uint4 v = kr[lane + i * 32];
        int kb = (lane + i * 32) * 8;
        __nv_bfloat162 p0 = *(__nv_bfloat162*)&v.x;
        __nv_bfloat162 p1 = *(__nv_bfloat162*)&v.y;
        __nv_bfloat162 p2 = *(__nv_bfloat162*)&v.z;
        __nv_bfloat162 p3 = *(__nv_bfloat162*)&v.w;
        s += __bfloat162float(p0.x) * hs[kb] + __bfloat162float(p0.y) * hs[kb + 1] +
             __bfloat162float(p1.x) * hs[kb + 2] + __bfloat162float(p1.y) * hs[kb + 3] +
             __bfloat162float(p2.x) * hs[kb + 4] + __bfloat162float(p2.y) * hs[kb + 5] +
             __bfloat162float(p3.x) * hs[kb + 6] + __bfloat162float(p3.y) * hs[kb + 7];
    }
#pragma unroll
    for (int o = 16; o; o >>= 1) s += __shfl_xor_sync(0xffffffffu, s, o);
    if (lane == 0) d_att[n * LL + l] = s;
}

// ---------------- attention part 2: softmax + ctx + x0 build ----------------
__global__ void softctx_kernel(const int* __restrict__ captions, const float* __restrict__ emb,
                               int next_step) {
    int n = blockIdx.x;
    int tid = threadIdx.x;
    int wid = tid >> 5, lane = tid & 31;
    __shared__ float e[LL];
    __shared__ float red[8], red2[8];
    float v = (tid < LL) ? d_att[n * LL + tid] : -3.4e38f;
    float m = v;
#pragma unroll
    for (int o = 16; o; o >>= 1) m = fmaxf(m, __shfl_xor_sync(0xffffffffu, m, o));
    if (lane == 0) red[wid] = m;
    __syncthreads();
    if (tid < 8) {
        float mm = red[tid];
#pragma unroll
        for (int o = 4; o; o >>= 1) mm = fmaxf(mm, __shfl_xor_sync(0xffu, mm, o));
        if (tid == 0) red[0] = mm;
    }
    __syncthreads();
    float gm = red[0];
    float ex = (tid < LL) ? expf(v - gm) : 0.f;
    float s = ex;
#pragma unroll
    for (int o = 16; o; o >>= 1) s += __shfl_xor_sync(0xffffffffu, s, o);
    if (lane == 0) red2[wid] = s;
    __syncthreads();
    if (tid < 8) {
        float ss = red2[tid];
#pragma unroll
        for (int o = 4; o; o >>= 1) ss += __shfl_xor_sync(0xffu, ss, o);
        if (tid == 0) red2[0] = ss;
    }
    __syncthreads();
    if (tid < LL) e[tid] = ex / red2[0];
    __syncthreads();
    int col = blockIdx.y * 256 + tid;
    const __nv_bfloat16* vp = d_vbf + (long)n * LL * PROJD + col;
    float acc = 0.f;
#pragma unroll 4
    for (int l = 0; l < LL; l++) acc += e[l] * __bfloat162float(vp[(long)l * PROJD]);
    d_xc0[n * 2560 + 512 + col] = __float2half_rn(acc);
    if (blockIdx.y == 0) {
        int tok = captions[n * TT + next_step];
        for (int k = tid; k < EMB; k += 256)
            d_xc0[n * 2560 + k] = __float2half_rn(emb[(long)tok * EMB + k]);
    }
}

// ---------------- projection (bf16 mma, 4-stage): out = hlast @ out_W^T ----------------
#define PSTAGE 20480
#define PJ_SMEM (4 * PSTAGE)

__device__ __forceinline__ void mma_bf16(float* c, const uint32_t* a, uint32_t b0, uint32_t b1) {
    asm volatile(
        "mma.sync.aligned.m16n8k16.row.col.f32.bf16.bf16.f32 "
        "{%0,%1,%2,%3}, {%4,%5,%6,%7}, {%8,%9}, {%0,%1,%2,%3};"
        : "+f"(c[0]), "+f"(c[1]), "+f"(c[2]), "+f"(c[3])
        : "r"(a[0]), "r"(a[1]), "r"(a[2]), "r"(a[3]), "r"(b0), "r"(b1));
}

__device__ __forceinline__ void proj_ld(uint32_t st, int bm, int bn, int k0, int tid) {
#pragma unroll
    for (int i = 0; i < 2; i++) {
        int gI = tid + i * 256;
        int row = gI >> 2, c = gI & 3;
        CPA16(st + row * 80 + c * 16, d_hlastb + (long)(bm * 128 + row) * DEC + k0 + c * 8);
    }
#pragma unroll
    for (int i = 0; i < 2; i++) {
        int gI = tid + i * 256;
        int row = gI >> 2, c = gI & 3;
        CPA16(st + 10240 + row * 80 + c * 16, d_pw + (long)(bn * 128 + row) * DEC + k0 + c * 8);
    }
}

__global__ __launch_bounds__(256) void proj_mma(const float* __restrict__ bias,
                                                float* __restrict__ out) {
    extern __shared__ char smem[];
    uint32_t sb = smem_u32(smem);
    const int tid = threadIdx.x;
    const int w = tid >> 5, lane = tid & 31, g = lane >> 2, tig = lane & 3;
    const int wm = w >> 2, wn = w & 3;
    const int bm = blockIdx.x, bn = blockIdx.y;

    float acc[4][4][4] = {};

    proj_ld(sb, bm, bn, 0, tid);  CP_COMMIT();
    proj_ld(sb + PSTAGE, bm, bn, 32, tid); CP_COMMIT();
    proj_ld(sb + 2 * PSTAGE, bm, bn, 64, tid); CP_COMMIT();

    for (int c = 0; c < 32; c++) {
        if (c + 2 < 32) CP_WAIT(2);
        else if (c + 1 < 32) CP_WAIT(1);
        else CP_WAIT(0);
        __syncthreads();
        if (c + 3 < 32) { proj_ld(sb + ((c + 3) & 3) * PSTAGE, bm, bn, (c + 3) * 32, tid); CP_COMMIT(); }
        const uint32_t* Au = (const uint32_t*)(smem + (c & 3) * PSTAGE);
        const uint32_t* Bu = (const uint32_t*)(smem + (c & 3) * PSTAGE + 10240);
#pragma unroll
        for (int ks = 0; ks < 2; ks++) {
            int k8 = ks * 8;
            uint32_t a[4][4];
#pragma unroll
            for (int mi = 0; mi < 4; mi++) {
                int r = (wm * 64 + mi * 16 + g) * 20;
                a[mi][0] = Au[r + k8 + tig];
                a[mi][1] = Au[r + 160 + k8 + tig];
                a[mi][2] = Au[r + k8 + tig + 4];
                a[mi][3] = Au[r + 160 + k8 + tig + 4];
            }
#pragma unroll
            for (int nj = 0; nj < 4; nj++) {
                int nr = (wn * 32 + nj * 8 + g) * 20;
                uint32_t b0 = Bu[nr + k8 + tig], b1 = Bu[nr + k8 + tig + 4];
#pragma unroll
                for (int mi = 0; mi < 4; mi++) mma_bf16(acc[mi][nj], a[mi], b0, b1);
            }
        }
    }

#pragma unroll
    for (int mi = 0; mi < 4; mi++) {
#pragma unroll
        for (int nj = 0; nj < 4; nj++) {
            int m0 = bm * 128 + wm * 64 + mi * 16 + g;
            int vv = bn * 128 + wn * 32 + nj * 8 + tig * 2;
            float b0 = bias[vv], b1 = bias[vv + 1];
            {
                int step = m0 >> 6, nn = m0 & 63;
                *(float2*)(out + ((long)nn * TT + step + 1) * VOC + vv) =
                    make_float2(acc[mi][nj][0] + b0, acc[mi][nj][1] + b1);
            }
            {
                int m1 = m0 + 8;
                int step = m1 >> 6, nn = m1 & 63;
                *(float2*)(out + ((long)nn * TT + step + 1) * VOC + vv) =
                    make_float2(acc[mi][nj][2] + b0, acc[mi][nj][3] + b1);
            }
        }
    }
}

// ---------------- launch ----------------
extern "C" void kernel_launch(void* const* d_in, const int* in_sizes, int n_in,
                              void* d_out, int out_size) {
    int sh = (n_in >= 19) ? 0 : 1;
    const float* keys     = (const float*)d_in[0];
    const float* values   = (const float*)d_in[1];
    const int*   captions = (const int*)d_in[3];
    const float* emb      = (const float*)d_in[5 - sh];
    const float* W_ih0    = (const float*)d_in[6 - sh];
    const float* W_hh0    = (const float*)d_in[7 - sh];
    const float* b_ih0    = (const float*)d_in[8 - sh];
    const float* b_hh0    = (const float*)d_in[9 - sh];
    const float* W_ih_r   = (const float*)d_in[10 - sh];
    const float* W_hh_r   = (const float*)d_in[11 - sh];
    const float* b_ih_r   = (const float*)d_in[12 - sh];
    const float* b_hh_r   = (const float*)d_in[13 - sh];
    const float* out_W    = (const float*)d_in[14 - sh];
    const float* out_b    = (const float*)d_in[15 - sh];
    const float* init_h   = (const float*)d_in[16 - sh];
    const float* init_c   = (const float*)d_in[17 - sh];
    const float* init_ctx = (const float*)d_in[18 - sh];
    float* out = (float*)d_out;

    cudaFuncSetAttribute(lstm_fused<0>, cudaFuncAttributeMaxDynamicSharedMemorySize, LS_SMEM);
    cudaFuncSetAttribute(lstm_fused<1>, cudaFuncAttributeMaxDynamicSharedMemorySize, LS_SMEM);
    cudaFuncSetAttribute(lstm_fused<2>, cudaFuncAttributeMaxDynamicSharedMemorySize, LS_SMEM);
    cudaFuncSetAttribute(proj_mma, cudaFuncAttributeMaxDynamicSharedMemorySize, PJ_SMEM);

    conv_all<<<2048, 256>>>(W_ih0, W_hh0, W_ih_r, W_hh_r,
                            (const float4*)out_W, (const float4*)keys, (const float4*)values,
                            (const float4*)b_ih0, (const float4*)b_hh0,
                            (const float4*)b_ih_r, (const float4*)b_hh_r);

    init_state<<<640, 256>>>(init_h, init_c, init_ctx, emb);
    out0_kernel<<<(NB * VOC + 255) / 256, 256>>>(out);

    for (int s = 0; s < NSTEP; s++) {
        lstm_fused<0><<<128, 256, LS_SMEM>>>(s);
        lstm_fused<1><<<128, 256, LS_SMEM>>>(s);
        lstm_fused<2><<<128, 256, LS_SMEM>>>(s);
        energy_kernel<<<dim3(64, 25), 256>>>();
        softctx_kernel<<<dim3(64, 4), 256>>>(captions, emb, s + 1);
    }

    proj_mma<<<dim3(12, 250), 256, PJ_SMEM>>>(out_b, out);
}